// round 2
// baseline (speedup 1.0000x reference)
#include <cuda_runtime.h>
#include <math.h>

#define BB   32
#define PP   21824
#define NCLS 80
#define KTOP 1000

// ---------------- scratch (static device globals; no allocation) -------------
__device__ float  g_score[BB * PP];
__device__ int    g_class[BB * PP];
__device__ float4 g_box[BB * PP];

struct Ptrs {
    const float* cls[5];
    const float* cen[5];
    const float* reg[5];
};

// ---- XLA:CPU-style expf: Cephes/Eigen polynomial, strict mul/add (no FMA) ---
__device__ __forceinline__ float xla_expf(float x) {
    x = fminf(x, 88.3762626647950f);
    x = fmaxf(x, -88.3762626647949f);
    float fx = __fadd_rn(__fmul_rn(x, 1.44269504088896341f), 0.5f);
    fx = floorf(fx);
    float tmp = __fmul_rn(fx, 0.693359375f);
    float z   = __fmul_rn(fx, -2.12194440e-4f);
    float xr  = __fsub_rn(x, tmp);
    xr = __fsub_rn(xr, z);
    z  = __fmul_rn(xr, xr);
    float y = 1.9875691500e-4f;
    y = __fadd_rn(__fmul_rn(y, xr), 1.3981999507e-3f);
    y = __fadd_rn(__fmul_rn(y, xr), 8.3334519073e-3f);
    y = __fadd_rn(__fmul_rn(y, xr), 4.1665795894e-2f);
    y = __fadd_rn(__fmul_rn(y, xr), 1.6666665459e-1f);
    y = __fadd_rn(__fmul_rn(y, xr), 5.0000001201e-1f);
    y = __fadd_rn(__fmul_rn(y, z), xr);
    y = __fadd_rn(y, 1.0f);
    int n = (int)fx;
    float p2n = __uint_as_float((unsigned)(n + 127) << 23);
    return __fmul_rn(y, p2n);
}
// logistic(x) = 1 / (1 + exp(-x)) — exp form (XLA LogisticExpander)
__device__ __forceinline__ float xla_sigmoid(float x) {
    float e = xla_expf(-x);
    return __fdiv_rn(1.0f, __fadd_rn(1.0f, e));
}

// ---------------- kernel 1: streaming score / argmax / box decode ------------
__global__ void score_kernel(Ptrs ps) {
    const int Q = (BB * PP) / 4;
    int gid = blockIdx.x * blockDim.x + threadIdx.x;
    if (gid >= Q) return;
    const int per = PP / 4;
    int b = gid / per;
    int p = (gid - b * per) * 4;

    int start, HW, W, S, lvl;
    if      (p < 16384) { lvl = 0; start = 0;     HW = 16384; W = 128; S = 8;   }
    else if (p < 20480) { lvl = 1; start = 16384; HW = 4096;  W = 64;  S = 16;  }
    else if (p < 21504) { lvl = 2; start = 20480; HW = 1024;  W = 32;  S = 32;  }
    else if (p < 21760) { lvl = 3; start = 21504; HW = 256;   W = 16;  S = 64;  }
    else                { lvl = 4; start = 21760; HW = 64;    W = 8;   S = 128; }

    int local = p - start;
    int hw4 = HW >> 2, l4 = local >> 2;

    const float4* cls = (const float4*)ps.cls[lvl];
    int cbase = (b * NCLS) * hw4 + l4;

    // streaming top-1 (value+index, first-max-wins) + top-2 value per lane
    float4 v0 = cls[cbase];
    float mx[4] = { v0.x, v0.y, v0.z, v0.w };
    float m2[4] = { -1e30f, -1e30f, -1e30f, -1e30f };
    int   am[4] = { 0, 0, 0, 0 };
#pragma unroll 4
    for (int c = 1; c < NCLS; c++) {
        float4 v = cls[cbase + c * hw4];
        float vv[4] = { v.x, v.y, v.z, v.w };
#pragma unroll
        for (int k = 0; k < 4; k++) {
            if (vv[k] > mx[k]) { m2[k] = mx[k]; mx[k] = vv[k]; am[k] = c; }
            else               { m2[k] = fmaxf(m2[k], vv[k]); }
        }
    }
    float4 cen = ((const float4*)ps.cen[lvl])[b * hw4 + l4];
    const float4* rg = (const float4*)ps.reg[lvl];
    int rbase = (b * 4) * hw4 + l4;
    float4 rl = rg[rbase], rt = rg[rbase + hw4];
    float4 rr = rg[rbase + 2 * hw4], rb = rg[rbase + 3 * hw4];

    float cenv[4] = { cen.x, cen.y, cen.z, cen.w };
    float lv[4] = { rl.x, rl.y, rl.z, rl.w };
    float tv[4] = { rt.x, rt.y, rt.z, rt.w };
    float rv[4] = { rr.x, rr.y, rr.z, rr.w };
    float bv[4] = { rb.x, rb.y, rb.z, rb.w };

#pragma unroll
    for (int k = 0; k < 4; k++) {
        int pp = local + k;
        int y = pp / W, x = pp - y * W;
        float cx = (float)(x * S + (S >> 1));
        float cy = (float)(y * S + (S >> 1));

        float mxS; int cls_id;
        if (mx[k] - m2[k] < 2e-4f) {
            // rare: near-tie — replicate reference argmax over sigmoid exactly
            const float* cp = ps.cls[lvl] + (long)(b * NCLS) * HW + local + k;
            float bestS = -1.0f; int bestC = 0;
            for (int c = 0; c < NCLS; c++) {
                float Sv = xla_sigmoid(cp[(long)c * HW]);
                if (Sv > bestS) { bestS = Sv; bestC = c; }
            }
            mxS = bestS; cls_id = bestC;
        } else {
            mxS = xla_sigmoid(mx[k]); cls_id = am[k];
        }
        float cS = xla_sigmoid(cenv[k]);
        float s = sqrtf(__fmul_rn(mxS, cS));
        int gi = b * PP + p + k;
        g_score[gi] = s;
        g_class[gi] = cls_id + 1;
        g_box[gi] = make_float4(cx - lv[k], cy - tv[k], cx + rv[k], cy + bv[k]);
    }
}

// ---------------- kernel 2: per-batch radix-select top-1000 + sort + NMS -----
__device__ __forceinline__ void bitonic1024_desc(unsigned long long* a, int tid) {
    for (int k = 2; k <= 1024; k <<= 1) {
        for (int j = k >> 1; j > 0; j >>= 1) {
            int ixj = tid ^ j;
            if (ixj > tid) {
                unsigned long long x = a[tid], y = a[ixj];
                if (((tid & k) == 0) ? (x < y) : (x > y)) { a[tid] = y; a[ixj] = x; }
            }
            __syncthreads();
        }
    }
}

__global__ __launch_bounds__(1024) void topk_nms_kernel(float* out) {
    __shared__ unsigned long long selkeys[1024];
    __shared__ unsigned long long bbuf[1024];     // aliased as 2048-bin histogram
    int* hist = (int*)bbuf;
    __shared__ float sbox[KTOP * 4];
    __shared__ float sarea[KTOP];
    __shared__ int   scls[KTOP];
    __shared__ int   skeep[KTOP];
    __shared__ float swmax[32];
    __shared__ float sMx;
    __shared__ int   sT1, sT2, sHistT1, csel, cbuf;

    const int b = blockIdx.x, tid = threadIdx.x, nt = 1024;
    const float* sc = g_score + b * PP;

    // --- histogram over top-11 bits of (positive) score bits ---
    for (int i = tid; i < 2048; i += nt) hist[i] = 0;
    __syncthreads();
    for (int p = tid; p < PP; p += nt)
        atomicAdd(&hist[__float_as_uint(sc[p]) >> 21], 1);
    __syncthreads();
    if (tid == 0) {
        int cum = 0, T1 = 0;
        for (int bin = 2047; bin >= 0; bin--) {
            int c = hist[bin];
            if (cum + c >= KTOP) { T1 = bin; break; }
            cum += c;
        }
        sT1 = T1; sHistT1 = hist[T1]; csel = cum; // strict-gt count
    }
    __syncthreads();
    const int T1 = sT1;
    const bool refine = (sHistT1 > 1024);
    int T2 = -1;
    int directGT = csel;
    __syncthreads();

    if (refine) {
        for (int i = tid; i < 2048; i += nt) hist[i] = 0;
        __syncthreads();
        for (int p = tid; p < PP; p += nt) {
            unsigned bits = __float_as_uint(sc[p]);
            if ((int)(bits >> 21) == T1) atomicAdd(&hist[(bits >> 10) & 2047], 1);
        }
        __syncthreads();
        if (tid == 0) {
            int need1 = KTOP - directGT;
            int cum = 0, t2 = 0;
            for (int bin = 2047; bin >= 0; bin--) {
                int c = hist[bin];
                if (cum + c >= need1) { t2 = bin; break; }
                cum += c;
            }
            sT2 = t2;
        }
        __syncthreads();
        T2 = sT2;
    }

    if (tid == 0) { csel = 0; cbuf = 0; }
    __syncthreads();

    // --- compaction: strict winners -> selkeys, boundary-bin -> bbuf ---
    for (int p = tid; p < PP; p += nt) {
        unsigned bits = __float_as_uint(sc[p]);
        int bin = bits >> 21;
        if (bin < T1) continue;
        unsigned long long key =
            ((unsigned long long)bits << 32) | (unsigned long long)(0xFFFFFFFFu - (unsigned)p);
        bool direct, bound;
        if (refine) {
            int sub = (bits >> 10) & 2047;
            direct = (bin > T1) || (sub > T2);
            bound  = (bin == T1) && (sub == T2);
        } else {
            direct = (bin > T1);
            bound  = (bin == T1);
        }
        if (direct) {
            int pos = atomicAdd(&csel, 1);
            if (pos < 1024) selkeys[pos] = key;
        } else if (bound) {
            int pos = atomicAdd(&cbuf, 1);
            if (pos < 1024) bbuf[pos] = key;
        }
    }
    __syncthreads();
    const int nsel = min(csel, 1000);
    const int nb = min(cbuf, 1024);

    for (int i = tid; i < 1024; i += nt) if (i >= nb) bbuf[i] = 0ULL;
    __syncthreads();
    bitonic1024_desc(bbuf, tid);
    {
        int i = tid;
        if (i >= nsel && i < KTOP) selkeys[i] = bbuf[i - nsel];
        else if (i >= KTOP)        selkeys[i] = 0ULL;
    }
    __syncthreads();
    bitonic1024_desc(selkeys, tid);

    // --- gather + emit sc / cl / bx; stage RAW boxes in shared ---
    float* osc = out;
    float* ocl = out + BB * KTOP;
    float* obx = out + 2 * BB * KTOP;
    float* okp = out + 6 * BB * KTOP;
    float localmax = -1e30f;
    if (tid < KTOP) {
        int i = tid;
        unsigned long long key = selkeys[i];
        float s = __uint_as_float((unsigned)(key >> 32));
        unsigned idx = 0xFFFFFFFFu - (unsigned)(key & 0xFFFFFFFFu);
        if (idx >= PP) idx = 0;
        int gi = b * PP + (int)idx;
        int c = g_class[gi];
        float4 bx = g_box[gi];
        osc[b * KTOP + i] = s;
        ocl[b * KTOP + i] = (float)c;
        ((float4*)obx)[b * KTOP + i] = bx;
        scls[i] = c;
        sbox[i * 4 + 0] = bx.x; sbox[i * 4 + 1] = bx.y;
        sbox[i * 4 + 2] = bx.z; sbox[i * 4 + 3] = bx.w;
        skeep[i] = (s >= 0.05f) ? 1 : 0;
        localmax = fmaxf(fmaxf(bx.x, bx.y), fmaxf(bx.z, bx.w));
    }
    // --- batch box max (reference: boxes.max() over selected [1000,4]) ---
#pragma unroll
    for (int o = 16; o > 0; o >>= 1)
        localmax = fmaxf(localmax, __shfl_xor_sync(0xFFFFFFFFu, localmax, o));
    if ((tid & 31) == 0) swmax[tid >> 5] = localmax;
    __syncthreads();
    if (tid == 0) {
        float m = swmax[0];
        for (int w = 1; w < 32; w++) m = fmaxf(m, swmax[w]);
        sMx = m;
    }
    __syncthreads();

    // --- apply class offset (reference: boxes + (max+1)*class), areas --------
    {
        float m1 = __fadd_rn(sMx, 1.0f);
        if (tid < KTOP) {
            int i = tid;
            float off = __fmul_rn(m1, (float)scls[i]);
            float x1 = __fadd_rn(sbox[i * 4 + 0], off);
            float y1 = __fadd_rn(sbox[i * 4 + 1], off);
            float x2 = __fadd_rn(sbox[i * 4 + 2], off);
            float y2 = __fadd_rn(sbox[i * 4 + 3], off);
            sbox[i * 4 + 0] = x1; sbox[i * 4 + 1] = y1;
            sbox[i * 4 + 2] = x2; sbox[i * 4 + 3] = y2;
            sarea[i] = __fmul_rn(fmaxf(__fsub_rn(x2, x1), 0.f),
                                 fmaxf(__fsub_rn(y2, y1), 0.f));
        }
    }
    __syncthreads();

    // --- class-partitioned greedy NMS: one thread per class ---
    if (tid < NCLS) {
        const int myc = tid + 1;
        int kept[160]; int nk = 0;
        for (int i = 0; i < KTOP; i++) {
            if (scls[i] != myc || !skeep[i]) continue;
            float ax1 = sbox[i * 4], ay1 = sbox[i * 4 + 1];
            float ax2 = sbox[i * 4 + 2], ay2 = sbox[i * 4 + 3];
            float aa = sarea[i];
            bool sup = false;
            for (int t = 0; t < nk; t++) {
                int j = kept[t];
                float xx1 = fmaxf(ax1, sbox[j * 4]);
                float yy1 = fmaxf(ay1, sbox[j * 4 + 1]);
                float xx2 = fminf(ax2, sbox[j * 4 + 2]);
                float yy2 = fminf(ay2, sbox[j * 4 + 3]);
                float w = fmaxf(__fsub_rn(xx2, xx1), 0.f);
                float h = fmaxf(__fsub_rn(yy2, yy1), 0.f);
                float inter = __fmul_rn(w, h);
                // reference op order: ((a_i + a_j) - inter) + 1e-9
                float den = __fadd_rn(__fsub_rn(__fadd_rn(aa, sarea[j]), inter), 1e-9f);
                float iou = __fdiv_rn(inter, den);
                if (iou > 0.6f) { sup = true; break; }
            }
            if (sup) skeep[i] = 0;
            else if (nk < 160) kept[nk++] = i;
        }
    }
    __syncthreads();
    if (tid < KTOP)
        okp[b * KTOP + tid] = skeep[tid] ? 1.0f : 0.0f;
}

// ---------------- launch ------------------------------------------------------
extern "C" void kernel_launch(void* const* d_in, const int* in_sizes, int n_in,
                              void* d_out, int out_size) {
    Ptrs ps;
    for (int i = 0; i < 5; i++) {
        ps.cls[i] = (const float*)d_in[i];
        ps.cen[i] = (const float*)d_in[5 + i];
        ps.reg[i] = (const float*)d_in[10 + i];
    }
    const int Q = (BB * PP) / 4;
    score_kernel<<<(Q + 255) / 256, 256>>>(ps);
    topk_nms_kernel<<<BB, 1024>>>((float*)d_out);
}

// round 3
// speedup vs baseline: 3.2660x; 3.2660x over previous
#include <cuda_runtime.h>
#include <math.h>

#define BB   32
#define PP   21824
#define NCLS 80
#define KTOP 1000

// ---------------- scratch (static device globals; no allocation) -------------
__device__ float  g_score[BB * PP];
__device__ float4 g_box[BB * PP];

struct Ptrs {
    const float* cls[5];
    const float* cen[5];
    const float* reg[5];
};

// ---- XLA:CPU-style expf: Cephes/Eigen polynomial, strict mul/add (no FMA) ---
__device__ __forceinline__ float xla_expf(float x) {
    x = fminf(x, 88.3762626647950f);
    x = fmaxf(x, -88.3762626647949f);
    float fx = __fadd_rn(__fmul_rn(x, 1.44269504088896341f), 0.5f);
    fx = floorf(fx);
    float tmp = __fmul_rn(fx, 0.693359375f);
    float z   = __fmul_rn(fx, -2.12194440e-4f);
    float xr  = __fsub_rn(x, tmp);
    xr = __fsub_rn(xr, z);
    z  = __fmul_rn(xr, xr);
    float y = 1.9875691500e-4f;
    y = __fadd_rn(__fmul_rn(y, xr), 1.3981999507e-3f);
    y = __fadd_rn(__fmul_rn(y, xr), 8.3334519073e-3f);
    y = __fadd_rn(__fmul_rn(y, xr), 4.1665795894e-2f);
    y = __fadd_rn(__fmul_rn(y, xr), 1.6666665459e-1f);
    y = __fadd_rn(__fmul_rn(y, xr), 5.0000001201e-1f);
    y = __fadd_rn(__fmul_rn(y, z), xr);
    y = __fadd_rn(y, 1.0f);
    int n = (int)fx;
    float p2n = __uint_as_float((unsigned)(n + 127) << 23);
    return __fmul_rn(y, p2n);
}
__device__ __forceinline__ float xla_sigmoid(float x) {
    float e = xla_expf(-x);
    return __fdiv_rn(1.0f, __fadd_rn(1.0f, e));
}

__device__ __forceinline__ void level_of(int p, int& lvl, int& start, int& HW,
                                         int& W, int& S) {
    if      (p < 16384) { lvl = 0; start = 0;     HW = 16384; W = 128; S = 8;   }
    else if (p < 20480) { lvl = 1; start = 16384; HW = 4096;  W = 64;  S = 16;  }
    else if (p < 21504) { lvl = 2; start = 20480; HW = 1024;  W = 32;  S = 32;  }
    else if (p < 21760) { lvl = 3; start = 21504; HW = 256;   W = 16;  S = 64;  }
    else                { lvl = 4; start = 21760; HW = 64;    W = 8;   S = 128; }
}

// ---------------- kernel 1: streaming max / score / box decode ---------------
// One thread per 4 consecutive points. Max over logits only (1 FMNMX/element);
// argmax is deferred to kernel 2 for the 1000 selected points per batch.
__global__ void score_kernel(Ptrs ps) {
    const int Q = (BB * PP) / 4;
    int gid = blockIdx.x * blockDim.x + threadIdx.x;
    if (gid >= Q) return;
    const int per = PP / 4;
    int b = gid / per;
    int p = (gid - b * per) * 4;

    int lvl, start, HW, W, S;
    level_of(p, lvl, start, HW, W, S);
    int local = p - start;
    int hw4 = HW >> 2, l4 = local >> 2;

    const float4* cls = (const float4*)ps.cls[lvl];
    const float4* cp = cls + (b * NCLS) * hw4 + l4;
    float4 mx = cp[0];
#pragma unroll 8
    for (int c = 1; c < NCLS; c++) {
        float4 v = cp[c * hw4];
        mx.x = fmaxf(mx.x, v.x);
        mx.y = fmaxf(mx.y, v.y);
        mx.z = fmaxf(mx.z, v.z);
        mx.w = fmaxf(mx.w, v.w);
    }
    float4 cen = ((const float4*)ps.cen[lvl])[b * hw4 + l4];
    const float4* rg = (const float4*)ps.reg[lvl];
    int rbase = (b * 4) * hw4 + l4;
    float4 rl = rg[rbase], rt = rg[rbase + hw4];
    float4 rr = rg[rbase + 2 * hw4], rb = rg[rbase + 3 * hw4];

    float mxv[4]  = { mx.x, mx.y, mx.z, mx.w };
    float cenv[4] = { cen.x, cen.y, cen.z, cen.w };
    float lv[4] = { rl.x, rl.y, rl.z, rl.w };
    float tv[4] = { rt.x, rt.y, rt.z, rt.w };
    float rv[4] = { rr.x, rr.y, rr.z, rr.w };
    float bv[4] = { rb.x, rb.y, rb.z, rb.w };

    float sco[4];
#pragma unroll
    for (int k = 0; k < 4; k++) {
        int pp = local + k;
        int y = pp / W, x = pp - y * W;
        float cx = (float)(x * S + (S >> 1));
        float cy = (float)(y * S + (S >> 1));
        float s = sqrtf(__fmul_rn(xla_sigmoid(mxv[k]), xla_sigmoid(cenv[k])));
        sco[k] = s;
        g_box[b * PP + p + k] = make_float4(cx - lv[k], cy - tv[k], cx + rv[k], cy + bv[k]);
    }
    *(float4*)(g_score + b * PP + p) = make_float4(sco[0], sco[1], sco[2], sco[3]);
}

// ---------------- kernel 2: topk + argmax(selected) + bucketed NMS -----------
__device__ __forceinline__ void bitonic1024_desc(unsigned long long* a, int tid) {
    for (int k = 2; k <= 1024; k <<= 1) {
        for (int j = k >> 1; j > 0; j >>= 1) {
            int ixj = tid ^ j;
            if (ixj > tid) {
                unsigned long long x = a[tid], y = a[ixj];
                if (((tid & k) == 0) ? (x < y) : (x > y)) { a[tid] = y; a[ixj] = x; }
            }
            __syncthreads();
        }
    }
}
__device__ __forceinline__ void bitonic1024_asc_u32(unsigned* a, int tid) {
    for (int k = 2; k <= 1024; k <<= 1) {
        for (int j = k >> 1; j > 0; j >>= 1) {
            int ixj = tid ^ j;
            if (ixj > tid) {
                unsigned x = a[tid], y = a[ixj];
                if (((tid & k) == 0) ? (x > y) : (x < y)) { a[tid] = y; a[ixj] = x; }
            }
            __syncthreads();
        }
    }
}

__global__ __launch_bounds__(1024) void topk_nms_kernel(Ptrs ps, float* out) {
    __shared__ unsigned long long selkeys[1024];
    __shared__ unsigned long long bbuf[1024];  // aliases: hist / keys+klist
    int*      hist = (int*)bbuf;
    unsigned* keys = (unsigned*)bbuf;          // [0..1023]
    unsigned* klist = ((unsigned*)bbuf) + 1024;// [0..1023]
    __shared__ float sbox[KTOP * 4];
    __shared__ float sarea[KTOP];
    __shared__ int   scls[KTOP];
    __shared__ int   skeep[KTOP];
    __shared__ int   sidx[KTOP];
    __shared__ int   cnt[NCLS], off[NCLS + 1];
    __shared__ float swmax[32];
    __shared__ float sMx;
    __shared__ int   sT1, sT2, sHistT1, csel, cbuf;

    const int b = blockIdx.x, tid = threadIdx.x, nt = 1024;
    const int lane = tid & 31, wid = tid >> 5;
    const float* sc = g_score + b * PP;

    // ---- stage 1: radix-select top-1000 (histogram over top-11 score bits) --
    for (int i = tid; i < 2048; i += nt) hist[i] = 0;
    __syncthreads();
    for (int p = tid; p < PP; p += nt)
        atomicAdd(&hist[__float_as_uint(sc[p]) >> 21], 1);
    __syncthreads();
    if (tid == 0) {
        int cum = 0, T1 = 0;
        for (int bin = 2047; bin >= 0; bin--) {
            int c = hist[bin];
            if (cum + c >= KTOP) { T1 = bin; break; }
            cum += c;
        }
        sT1 = T1; sHistT1 = hist[T1]; csel = cum;
    }
    __syncthreads();
    const int T1 = sT1;
    const bool refine = (sHistT1 > 1024);
    int T2 = -1;
    int directGT = csel;
    __syncthreads();

    if (refine) {
        for (int i = tid; i < 2048; i += nt) hist[i] = 0;
        __syncthreads();
        for (int p = tid; p < PP; p += nt) {
            unsigned bits = __float_as_uint(sc[p]);
            if ((int)(bits >> 21) == T1) atomicAdd(&hist[(bits >> 10) & 2047], 1);
        }
        __syncthreads();
        if (tid == 0) {
            int need1 = KTOP - directGT;
            int cum = 0, t2 = 0;
            for (int bin = 2047; bin >= 0; bin--) {
                int c = hist[bin];
                if (cum + c >= need1) { t2 = bin; break; }
                cum += c;
            }
            sT2 = t2;
        }
        __syncthreads();
        T2 = sT2;
    }
    if (tid == 0) { csel = 0; cbuf = 0; }
    __syncthreads();

    for (int p = tid; p < PP; p += nt) {
        unsigned bits = __float_as_uint(sc[p]);
        int bin = bits >> 21;
        if (bin < T1) continue;
        unsigned long long key =
            ((unsigned long long)bits << 32) | (unsigned long long)(0xFFFFFFFFu - (unsigned)p);
        bool direct, bound;
        if (refine) {
            int sub = (bits >> 10) & 2047;
            direct = (bin > T1) || (sub > T2);
            bound  = (bin == T1) && (sub == T2);
        } else {
            direct = (bin > T1);
            bound  = (bin == T1);
        }
        if (direct) {
            int pos = atomicAdd(&csel, 1);
            if (pos < 1024) selkeys[pos] = key;
        } else if (bound) {
            int pos = atomicAdd(&cbuf, 1);
            if (pos < 1024) bbuf[pos] = key;
        }
    }
    __syncthreads();
    const int nsel = min(csel, 1000);
    const int nb = min(cbuf, 1024);
    for (int i = tid; i < 1024; i += nt) if (i >= nb) bbuf[i] = 0ULL;
    __syncthreads();
    bitonic1024_desc(bbuf, tid);
    {
        int i = tid;
        if (i >= nsel && i < KTOP) selkeys[i] = bbuf[i - nsel];
        else if (i >= KTOP)        selkeys[i] = 0ULL;
    }
    __syncthreads();
    bitonic1024_desc(selkeys, tid);

    // ---- stage 2: gather selected, emit sc/bx, stage NMS inputs -------------
    float* osc = out;
    float* ocl = out + BB * KTOP;
    float* obx = out + 2 * BB * KTOP;
    float* okp = out + 6 * BB * KTOP;
    float localmax = -1e30f;
    if (tid < KTOP) {
        int i = tid;
        unsigned long long key = selkeys[i];
        float s = __uint_as_float((unsigned)(key >> 32));
        unsigned idx = 0xFFFFFFFFu - (unsigned)(key & 0xFFFFFFFFu);
        if (idx >= PP) idx = 0;
        float4 bx = g_box[b * PP + (int)idx];
        osc[b * KTOP + i] = s;
        ((float4*)obx)[b * KTOP + i] = bx;
        sidx[i] = (int)idx;
        sbox[i * 4 + 0] = bx.x; sbox[i * 4 + 1] = bx.y;
        sbox[i * 4 + 2] = bx.z; sbox[i * 4 + 3] = bx.w;
        skeep[i] = (s >= 0.05f) ? 1 : 0;
        localmax = fmaxf(fmaxf(bx.x, bx.y), fmaxf(bx.z, bx.w));
    }
#pragma unroll
    for (int o = 16; o > 0; o >>= 1)
        localmax = fmaxf(localmax, __shfl_xor_sync(0xFFFFFFFFu, localmax, o));
    if (lane == 0) swmax[wid] = localmax;
    __syncthreads();
    if (tid == 0) {
        float m = swmax[0];
        for (int w = 1; w < 32; w++) m = fmaxf(m, swmax[w]);
        sMx = m;
    }
    __syncthreads();

    // ---- stage 3: argmax over sigmoid for selected points (warp per point) --
    for (int i = wid; i < KTOP; i += 32) {
        int p = sidx[i];
        int lvl, start, HW, W, S;
        level_of(p, lvl, start, HW, W, S);
        int local = p - start;
        const float* base = ps.cls[lvl] + (b * NCLS) * HW + local;
        float bestS = -1.0f; int bestC = 127;
        for (int c = lane; c < NCLS; c += 32) {
            float Sv = xla_sigmoid(base[c * HW]);
            if (Sv > bestS) { bestS = Sv; bestC = c; }  // ascending c: first-wins
        }
#pragma unroll
        for (int o = 16; o > 0; o >>= 1) {
            float oS = __shfl_xor_sync(0xFFFFFFFFu, bestS, o);
            int   oC = __shfl_xor_sync(0xFFFFFFFFu, bestC, o);
            if (oS > bestS || (oS == bestS && oC < bestC)) { bestS = oS; bestC = oC; }
        }
        if (lane == 0) {
            scls[i] = bestC + 1;
            ocl[b * KTOP + i] = (float)(bestC + 1);
        }
    }
    __syncthreads();

    // ---- stage 4: class offsets + areas (reference op order, no FMA) --------
    {
        float m1 = __fadd_rn(sMx, 1.0f);
        if (tid < KTOP) {
            int i = tid;
            float o2 = __fmul_rn(m1, (float)scls[i]);
            float x1 = __fadd_rn(sbox[i * 4 + 0], o2);
            float y1 = __fadd_rn(sbox[i * 4 + 1], o2);
            float x2 = __fadd_rn(sbox[i * 4 + 2], o2);
            float y2 = __fadd_rn(sbox[i * 4 + 3], o2);
            sbox[i * 4 + 0] = x1; sbox[i * 4 + 1] = y1;
            sbox[i * 4 + 2] = x2; sbox[i * 4 + 3] = y2;
            sarea[i] = __fmul_rn(fmaxf(__fsub_rn(x2, x1), 0.f),
                                 fmaxf(__fsub_rn(y2, y1), 0.f));
        }
    }
    // ---- stage 5: bucket valid candidates by class (stable via sort) --------
    if (tid < NCLS) cnt[tid] = 0;
    __syncthreads();   // also covers stage-4 writes
    {
        unsigned key = 0xFFFFFFFFu;
        if (tid < KTOP && skeep[tid]) {
            key = ((unsigned)(scls[tid] - 1) << 10) | (unsigned)tid;
            atomicAdd(&cnt[scls[tid] - 1], 1);
        }
        keys[tid] = key;
    }
    __syncthreads();
    if (tid == 0) {
        int acc = 0;
        for (int c = 0; c < NCLS; c++) { off[c] = acc; acc += cnt[c]; }
        off[NCLS] = acc;
    }
    bitonic1024_asc_u32(keys, tid);   // barrier inside orders off[] too

    // ---- stage 6: greedy NMS, one warp-task per class -----------------------
    for (int c = wid; c < NCLS; c += 32) {
        int o0 = off[c], n = off[c + 1] - o0;
        int nk = 0;
        for (int t = 0; t < n; t++) {
            int i = (int)(keys[o0 + t] & 1023u);
            float ax1 = sbox[i * 4 + 0], ay1 = sbox[i * 4 + 1];
            float ax2 = sbox[i * 4 + 2], ay2 = sbox[i * 4 + 3];
            float aa = sarea[i];
            bool sup = false;
            for (int kb = 0; kb < nk && !sup; kb += 32) {
                int kk = kb + lane;
                bool mysup = false;
                if (kk < nk) {
                    int j = (int)klist[o0 + kk];
                    float xx1 = fmaxf(ax1, sbox[j * 4 + 0]);
                    float yy1 = fmaxf(ay1, sbox[j * 4 + 1]);
                    float xx2 = fminf(ax2, sbox[j * 4 + 2]);
                    float yy2 = fminf(ay2, sbox[j * 4 + 3]);
                    float w = fmaxf(__fsub_rn(xx2, xx1), 0.f);
                    float h = fmaxf(__fsub_rn(yy2, yy1), 0.f);
                    float inter = __fmul_rn(w, h);
                    float den = __fadd_rn(__fsub_rn(__fadd_rn(aa, sarea[j]), inter), 1e-9f);
                    mysup = (__fdiv_rn(inter, den) > 0.6f);
                }
                if (__any_sync(0xFFFFFFFFu, mysup)) sup = true;
            }
            if (sup) {
                if (lane == 0) skeep[i] = 0;
            } else {
                if (lane == 0) klist[o0 + nk] = (unsigned)i;
                nk++;
            }
            __syncwarp();
        }
    }
    __syncthreads();
    if (tid < KTOP)
        okp[b * KTOP + tid] = skeep[tid] ? 1.0f : 0.0f;
}

// ---------------- launch ------------------------------------------------------
extern "C" void kernel_launch(void* const* d_in, const int* in_sizes, int n_in,
                              void* d_out, int out_size) {
    Ptrs ps;
    for (int i = 0; i < 5; i++) {
        ps.cls[i] = (const float*)d_in[i];
        ps.cen[i] = (const float*)d_in[5 + i];
        ps.reg[i] = (const float*)d_in[10 + i];
    }
    const int Q = (BB * PP) / 4;
    score_kernel<<<(Q + 255) / 256, 256>>>(ps);
    topk_nms_kernel<<<BB, 1024>>>(ps, (float*)d_out);
}

// round 5
// speedup vs baseline: 4.2124x; 1.2898x over previous
#include <cuda_runtime.h>
#include <math.h>

#define BB   32
#define PP   21824
#define NCLS 80
#define KTOP 1000

// ---------------- scratch (static device globals; no allocation) -------------
__device__ float  g_score[BB * PP];
__device__ float4 g_box[BB * PP];
__device__ int    g_selidx[BB * KTOP];

struct Ptrs {
    const float* cls[5];
    const float* cen[5];
    const float* reg[5];
};

// ---- XLA:CPU-style expf: Cephes/Eigen polynomial, strict mul/add (no FMA) ---
__device__ __forceinline__ float xla_expf(float x) {
    x = fminf(x, 88.3762626647950f);
    x = fmaxf(x, -88.3762626647949f);
    float fx = __fadd_rn(__fmul_rn(x, 1.44269504088896341f), 0.5f);
    fx = floorf(fx);
    float tmp = __fmul_rn(fx, 0.693359375f);
    float z   = __fmul_rn(fx, -2.12194440e-4f);
    float xr  = __fsub_rn(x, tmp);
    xr = __fsub_rn(xr, z);
    z  = __fmul_rn(xr, xr);
    float y = 1.9875691500e-4f;
    y = __fadd_rn(__fmul_rn(y, xr), 1.3981999507e-3f);
    y = __fadd_rn(__fmul_rn(y, xr), 8.3334519073e-3f);
    y = __fadd_rn(__fmul_rn(y, xr), 4.1665795894e-2f);
    y = __fadd_rn(__fmul_rn(y, xr), 1.6666665459e-1f);
    y = __fadd_rn(__fmul_rn(y, xr), 5.0000001201e-1f);
    y = __fadd_rn(__fmul_rn(y, z), xr);
    y = __fadd_rn(y, 1.0f);
    int n = (int)fx;
    float p2n = __uint_as_float((unsigned)(n + 127) << 23);
    return __fmul_rn(y, p2n);
}
__device__ __forceinline__ float xla_sigmoid(float x) {
    float e = xla_expf(-x);
    return __fdiv_rn(1.0f, __fadd_rn(1.0f, e));
}

__device__ __forceinline__ void level_of(int p, int& lvl, int& start, int& HW,
                                         int& W, int& S) {
    if      (p < 16384) { lvl = 0; start = 0;     HW = 16384; W = 128; S = 8;   }
    else if (p < 20480) { lvl = 1; start = 16384; HW = 4096;  W = 64;  S = 16;  }
    else if (p < 21504) { lvl = 2; start = 20480; HW = 1024;  W = 32;  S = 32;  }
    else if (p < 21760) { lvl = 3; start = 21504; HW = 256;   W = 16;  S = 64;  }
    else                { lvl = 4; start = 21760; HW = 64;    W = 8;   S = 128; }
}

// ---------------- kernel 1: streaming max / score / box decode ---------------
__global__ void score_kernel(Ptrs ps) {
    const int Q = (BB * PP) / 4;
    int gid = blockIdx.x * blockDim.x + threadIdx.x;
    if (gid >= Q) return;
    const int per = PP / 4;
    int b = gid / per;
    int p = (gid - b * per) * 4;

    int lvl, start, HW, W, S;
    level_of(p, lvl, start, HW, W, S);
    int local = p - start;
    int hw4 = HW >> 2, l4 = local >> 2;

    const float4* cls = (const float4*)ps.cls[lvl];
    const float4* cp = cls + (b * NCLS) * hw4 + l4;
    float4 mx = cp[0];
#pragma unroll 8
    for (int c = 1; c < NCLS; c++) {
        float4 v = cp[c * hw4];
        mx.x = fmaxf(mx.x, v.x);
        mx.y = fmaxf(mx.y, v.y);
        mx.z = fmaxf(mx.z, v.z);
        mx.w = fmaxf(mx.w, v.w);
    }
    float4 cen = ((const float4*)ps.cen[lvl])[b * hw4 + l4];
    const float4* rg = (const float4*)ps.reg[lvl];
    int rbase = (b * 4) * hw4 + l4;
    float4 rl = rg[rbase], rt = rg[rbase + hw4];
    float4 rr = rg[rbase + 2 * hw4], rb = rg[rbase + 3 * hw4];

    float mxv[4]  = { mx.x, mx.y, mx.z, mx.w };
    float cenv[4] = { cen.x, cen.y, cen.z, cen.w };
    float lv[4] = { rl.x, rl.y, rl.z, rl.w };
    float tv[4] = { rt.x, rt.y, rt.z, rt.w };
    float rv[4] = { rr.x, rr.y, rr.z, rr.w };
    float bv[4] = { rb.x, rb.y, rb.z, rb.w };

    float sco[4];
#pragma unroll
    for (int k = 0; k < 4; k++) {
        int pp = local + k;
        int y = pp / W, x = pp - y * W;
        float cx = (float)(x * S + (S >> 1));
        float cy = (float)(y * S + (S >> 1));
        sco[k] = sqrtf(__fmul_rn(xla_sigmoid(mxv[k]), xla_sigmoid(cenv[k])));
        g_box[b * PP + p + k] = make_float4(cx - lv[k], cy - tv[k], cx + rv[k], cy + bv[k]);
    }
    *(float4*)(g_score + b * PP + p) = make_float4(sco[0], sco[1], sco[2], sco[3]);
}

// ---------------- hybrid bitonic sorts (register stages for j<=16) -----------
__device__ __forceinline__ unsigned long long bx64(unsigned long long v, int j,
                                                   int k, int tid) {
    unsigned long long o = __shfl_xor_sync(0xFFFFFFFFu, v, j);
    bool takeMax = (((tid & j) == 0) == ((tid & k) == 0));  // desc regions
    return takeMax ? (o > v ? o : v) : (o < v ? o : v);
}
__device__ void sort1024_desc(unsigned long long* a, int tid) {
    unsigned long long v = a[tid];
#pragma unroll
    for (int k = 2; k <= 32; k <<= 1)
#pragma unroll
        for (int j = k >> 1; j >= 1; j >>= 1) v = bx64(v, j, k, tid);
    a[tid] = v;
    __syncthreads();
    for (int k = 64; k <= 1024; k <<= 1) {
        for (int j = k >> 1; j >= 32; j >>= 1) {
            int ixj = tid ^ j;
            if (ixj > tid) {
                unsigned long long x = a[tid], y = a[ixj];
                if (((tid & k) == 0) ? (x < y) : (x > y)) { a[tid] = y; a[ixj] = x; }
            }
            __syncthreads();
        }
        v = a[tid];
#pragma unroll
        for (int j = 16; j >= 1; j >>= 1) v = bx64(v, j, k, tid);
        a[tid] = v;
        __syncthreads();
    }
}
__device__ __forceinline__ unsigned bx32a(unsigned v, int j, int k, int tid) {
    unsigned o = __shfl_xor_sync(0xFFFFFFFFu, v, j);
    bool takeMin = (((tid & j) == 0) == ((tid & k) == 0));  // asc regions
    return takeMin ? (o < v ? o : v) : (o > v ? o : v);
}
__device__ void sort1024_asc_u32(unsigned* a, int tid) {
    unsigned v = a[tid];
#pragma unroll
    for (int k = 2; k <= 32; k <<= 1)
#pragma unroll
        for (int j = k >> 1; j >= 1; j >>= 1) v = bx32a(v, j, k, tid);
    a[tid] = v;
    __syncthreads();
    for (int k = 64; k <= 1024; k <<= 1) {
        for (int j = k >> 1; j >= 32; j >>= 1) {
            int ixj = tid ^ j;
            if (ixj > tid) {
                unsigned x = a[tid], y = a[ixj];
                if (((tid & k) == 0) ? (x > y) : (x < y)) { a[tid] = y; a[ixj] = x; }
            }
            __syncthreads();
        }
        v = a[tid];
#pragma unroll
        for (int j = 16; j >= 1; j >>= 1) v = bx32a(v, j, k, tid);
        a[tid] = v;
        __syncthreads();
    }
}

// ---------------- kernel 2a: per-batch radix-select + sort -------------------
__global__ __launch_bounds__(1024) void topk_kernel(float* out) {
    __shared__ unsigned long long selkeys[1024];
    __shared__ unsigned long long bbuf[1024];   // alias: 2048-bin histogram
    int* hist = (int*)bbuf;
    __shared__ int sT1, sT2, sHistT1, csel, cbuf;

    const int b = blockIdx.x, tid = threadIdx.x, nt = 1024;
    const int lane = tid & 31;
    const unsigned lmask = (1u << lane) - 1u;
    const float* sc = g_score + b * PP;
    const int NIT = (PP + nt - 1) / nt;

    for (int i = tid; i < 2048; i += nt) hist[i] = 0;
    __syncthreads();
    // warp-aggregated histogram over top-11 score bits
    for (int it = 0; it < NIT; it++) {
        int p = tid + it * nt;
        bool v = p < PP;
        int bin = v ? (int)(__float_as_uint(sc[p]) >> 21) : 0;
        unsigned bal = __ballot_sync(0xFFFFFFFFu, v);
        if (v) {
            unsigned m = __match_any_sync(bal, bin);
            if ((int)(__ffs(m) - 1) == lane) atomicAdd(&hist[bin], __popc(m));
        }
    }
    __syncthreads();
    if (tid == 0) {
        int cum = 0, T1 = 0;
        for (int bin = 2047; bin >= 0; bin--) {
            int c = hist[bin];
            if (cum + c >= KTOP) { T1 = bin; break; }
            cum += c;
        }
        sT1 = T1; sHistT1 = hist[T1]; csel = cum;
    }
    __syncthreads();
    const int T1 = sT1;
    const bool refine = (sHistT1 > 1024);
    int T2 = -1;
    int directGT = csel;
    __syncthreads();

    if (refine) {
        for (int i = tid; i < 2048; i += nt) hist[i] = 0;
        __syncthreads();
        for (int it = 0; it < NIT; it++) {
            int p = tid + it * nt;
            unsigned bits = (p < PP) ? __float_as_uint(sc[p]) : 0u;
            bool v = (p < PP) && ((int)(bits >> 21) == T1);
            int sub = (int)((bits >> 10) & 2047);
            unsigned bal = __ballot_sync(0xFFFFFFFFu, v);
            if (v) {
                unsigned m = __match_any_sync(bal, sub);
                if ((int)(__ffs(m) - 1) == lane) atomicAdd(&hist[sub], __popc(m));
            }
        }
        __syncthreads();
        if (tid == 0) {
            int need1 = KTOP - directGT;
            int cum = 0, t2 = 0;
            for (int bin = 2047; bin >= 0; bin--) {
                int c = hist[bin];
                if (cum + c >= need1) { t2 = bin; break; }
                cum += c;
            }
            sT2 = t2;
        }
        __syncthreads();
        T2 = sT2;
    }
    if (tid == 0) { csel = 0; cbuf = 0; }
    __syncthreads();

    // compaction (ballot-aggregated counter reservation)
    for (int it = 0; it < NIT; it++) {
        int p = tid + it * nt;
        bool valid = p < PP;
        unsigned bits = valid ? __float_as_uint(sc[p]) : 0u;
        int bin = (int)(bits >> 21);
        bool direct = false, bound = false;
        if (valid && bin >= T1) {
            if (refine) {
                int sub = (int)((bits >> 10) & 2047);
                direct = (bin > T1) || (sub > T2);
                bound  = (bin == T1) && (sub == T2);
            } else {
                direct = (bin > T1);
                bound  = (bin == T1);
            }
        }
        unsigned long long key =
            ((unsigned long long)bits << 32) | (unsigned long long)(0xFFFFFFFFu - (unsigned)p);
        unsigned bd = __ballot_sync(0xFFFFFFFFu, direct);
        if (bd) {
            int ldr = __ffs(bd) - 1, base = 0;
            if (lane == ldr) base = atomicAdd(&csel, __popc(bd));
            base = __shfl_sync(0xFFFFFFFFu, base, ldr);
            if (direct) {
                int pos = base + __popc(bd & lmask);
                if (pos < 1024) selkeys[pos] = key;
            }
        }
        unsigned bb = __ballot_sync(0xFFFFFFFFu, bound);
        if (bb) {
            int ldr = __ffs(bb) - 1, base = 0;
            if (lane == ldr) base = atomicAdd(&cbuf, __popc(bb));
            base = __shfl_sync(0xFFFFFFFFu, base, ldr);
            if (bound) {
                int pos = base + __popc(bb & lmask);
                if (pos < 1024) bbuf[pos] = key;
            }
        }
    }
    __syncthreads();
    const int nsel = min(csel, 1000);
    const int nb = min(cbuf, 1024);
    if (tid >= nb) bbuf[tid] = 0ULL;
    __syncthreads();
    sort1024_desc(bbuf, tid);
    {
        int i = tid;
        if (i >= nsel && i < KTOP) selkeys[i] = bbuf[i - nsel];
        else if (i >= KTOP)        selkeys[i] = 0ULL;
    }
    __syncthreads();
    sort1024_desc(selkeys, tid);

    // emit sc / bx / selidx
    float* osc = out;
    float* obx = out + 2 * BB * KTOP;
    if (tid < KTOP) {
        unsigned long long key = selkeys[tid];
        float s = __uint_as_float((unsigned)(key >> 32));
        unsigned idx = 0xFFFFFFFFu - (unsigned)(key & 0xFFFFFFFFu);
        if (idx >= PP) idx = 0;
        osc[b * KTOP + tid] = s;
        ((float4*)obx)[b * KTOP + tid] = g_box[b * PP + (int)idx];
        g_selidx[b * KTOP + tid] = (int)idx;
    }
}

// ---------------- kernel 2b: full-chip argmax over sigmoid (selected) --------
__global__ __launch_bounds__(256) void argmax_kernel(Ptrs ps, float* out) {
    int g = blockIdx.x * 8 + (threadIdx.x >> 5);   // one warp per selected point
    const int lane = threadIdx.x & 31;
    if (g >= BB * KTOP) return;
    int b = g / KTOP, i = g - b * KTOP;
    int p = g_selidx[g];
    int lvl, start, HW, W, S;
    level_of(p, lvl, start, HW, W, S);
    int local = p - start;
    const float* base = ps.cls[lvl] + (long)(b * NCLS) * HW + local;

    // three independent loads per lane (classes lane, lane+32, lane+64)
    float l0 = base[(long)lane * HW];
    float l1 = base[(long)(lane + 32) * HW];
    float l2 = (lane < 16) ? base[(long)(lane + 64) * HW] : 0.0f;

    float bestS = xla_sigmoid(l0); int bestC = lane;
    float s1 = xla_sigmoid(l1);
    if (s1 > bestS) { bestS = s1; bestC = lane + 32; }
    if (lane < 16) {
        float s2 = xla_sigmoid(l2);
        if (s2 > bestS) { bestS = s2; bestC = lane + 64; }
    }
#pragma unroll
    for (int o = 16; o > 0; o >>= 1) {
        float oS = __shfl_xor_sync(0xFFFFFFFFu, bestS, o);
        int   oC = __shfl_xor_sync(0xFFFFFFFFu, bestC, o);
        if (oS > bestS || (oS == bestS && oC < bestC)) { bestS = oS; bestC = oC; }
    }
    if (lane == 0)
        out[BB * KTOP + b * KTOP + i] = (float)(bestC + 1);  // ocl
}

// ---------------- kernel 2c: per-batch bucketed NMS --------------------------
__global__ __launch_bounds__(1024) void nms_kernel(float* out) {
    __shared__ float sbox[KTOP * 4];
    __shared__ float sarea[KTOP];
    __shared__ int   scls[KTOP];
    __shared__ int   skeep[KTOP];
    __shared__ unsigned keys[1024];
    __shared__ unsigned klist[1024];
    __shared__ int   cnt[NCLS], off[NCLS + 1];
    __shared__ float swmax[32];
    __shared__ float sMx;

    const int b = blockIdx.x, tid = threadIdx.x;
    const int lane = tid & 31, wid = tid >> 5;
    const float* osc = out;
    const float* ocl = out + BB * KTOP;
    const float* obx = out + 2 * BB * KTOP;
    float* okp = out + 6 * BB * KTOP;

    float localmax = -1e30f;
    if (tid < KTOP) {
        float s = osc[b * KTOP + tid];
        float4 bxv = ((const float4*)obx)[b * KTOP + tid];
        scls[tid] = (int)ocl[b * KTOP + tid];
        sbox[tid * 4 + 0] = bxv.x; sbox[tid * 4 + 1] = bxv.y;
        sbox[tid * 4 + 2] = bxv.z; sbox[tid * 4 + 3] = bxv.w;
        skeep[tid] = (s >= 0.05f) ? 1 : 0;
        localmax = fmaxf(fmaxf(bxv.x, bxv.y), fmaxf(bxv.z, bxv.w));
    }
#pragma unroll
    for (int o = 16; o > 0; o >>= 1)
        localmax = fmaxf(localmax, __shfl_xor_sync(0xFFFFFFFFu, localmax, o));
    if (lane == 0) swmax[wid] = localmax;
    __syncthreads();
    if (tid == 0) {
        float m = swmax[0];
        for (int w = 1; w < 32; w++) m = fmaxf(m, swmax[w]);
        sMx = m;
    }
    if (tid < NCLS) cnt[tid] = 0;
    __syncthreads();

    // class offsets + areas (reference op order, no FMA)
    {
        float m1 = __fadd_rn(sMx, 1.0f);
        if (tid < KTOP) {
            float o2 = __fmul_rn(m1, (float)scls[tid]);
            float x1 = __fadd_rn(sbox[tid * 4 + 0], o2);
            float y1 = __fadd_rn(sbox[tid * 4 + 1], o2);
            float x2 = __fadd_rn(sbox[tid * 4 + 2], o2);
            float y2 = __fadd_rn(sbox[tid * 4 + 3], o2);
            sbox[tid * 4 + 0] = x1; sbox[tid * 4 + 1] = y1;
            sbox[tid * 4 + 2] = x2; sbox[tid * 4 + 3] = y2;
            sarea[tid] = __fmul_rn(fmaxf(__fsub_rn(x2, x1), 0.f),
                                   fmaxf(__fsub_rn(y2, y1), 0.f));
        }
    }
    // bucket valid candidates by class (stable: sort (class<<10|rank) asc)
    {
        unsigned key = 0xFFFFFFFFu;
        if (tid < KTOP && skeep[tid]) {
            key = ((unsigned)(scls[tid] - 1) << 10) | (unsigned)tid;
            atomicAdd(&cnt[scls[tid] - 1], 1);
        }
        keys[tid] = key;
    }
    __syncthreads();
    if (tid == 0) {
        int acc = 0;
        for (int c = 0; c < NCLS; c++) { off[c] = acc; acc += cnt[c]; }
        off[NCLS] = acc;
    }
    sort1024_asc_u32(keys, tid);   // internal barriers order off[] too

    // greedy NMS, one warp-task per class
    for (int c = wid; c < NCLS; c += 32) {
        int o0 = off[c], n = off[c + 1] - o0;
        int nk = 0;
        for (int t = 0; t < n; t++) {
            int i = (int)(keys[o0 + t] & 1023u);
            float ax1 = sbox[i * 4 + 0], ay1 = sbox[i * 4 + 1];
            float ax2 = sbox[i * 4 + 2], ay2 = sbox[i * 4 + 3];
            float aa = sarea[i];
            bool sup = false;
            for (int kb = 0; kb < nk && !sup; kb += 32) {
                int kk = kb + lane;
                bool mysup = false;
                if (kk < nk) {
                    int j = (int)klist[o0 + kk];
                    float xx1 = fmaxf(ax1, sbox[j * 4 + 0]);
                    float yy1 = fmaxf(ay1, sbox[j * 4 + 1]);
                    float xx2 = fminf(ax2, sbox[j * 4 + 2]);
                    float yy2 = fminf(ay2, sbox[j * 4 + 3]);
                    float w = fmaxf(__fsub_rn(xx2, xx1), 0.f);
                    float h = fmaxf(__fsub_rn(yy2, yy1), 0.f);
                    float inter = __fmul_rn(w, h);
                    float den = __fadd_rn(__fsub_rn(__fadd_rn(aa, sarea[j]), inter), 1e-9f);
                    mysup = (__fdiv_rn(inter, den) > 0.6f);
                }
                if (__any_sync(0xFFFFFFFFu, mysup)) sup = true;
            }
            if (sup) {
                if (lane == 0) skeep[i] = 0;
            } else {
                if (lane == 0) klist[o0 + nk] = (unsigned)i;
                nk++;
            }
            __syncwarp();
        }
    }
    __syncthreads();
    if (tid < KTOP)
        okp[b * KTOP + tid] = skeep[tid] ? 1.0f : 0.0f;
}

// ---------------- launch ------------------------------------------------------
extern "C" void kernel_launch(void* const* d_in, const int* in_sizes, int n_in,
                              void* d_out, int out_size) {
    Ptrs ps;
    for (int i = 0; i < 5; i++) {
        ps.cls[i] = (const float*)d_in[i];
        ps.cen[i] = (const float*)d_in[5 + i];
        ps.reg[i] = (const float*)d_in[10 + i];
    }
    const int Q = (BB * PP) / 4;
    float* out = (float*)d_out;
    score_kernel<<<(Q + 255) / 256, 256>>>(ps);
    topk_kernel<<<BB, 1024>>>(out);
    argmax_kernel<<<(BB * KTOP + 7) / 8, 256>>>(ps, out);
    nms_kernel<<<BB, 1024>>>(out);
}